// round 13
// baseline (speedup 1.0000x reference)
#include <cuda_runtime.h>
#include <stdint.h>

#define H 2048
#define W 2048
#define KS 11
#define PS 10
#define PAD 5
#define HO 205                 // conv output: floor((2048+10-11)/10)+1
#define OUT 2255               // 205 * (PS+1)
#define CELLS (HO*HO)
#define ROWS_TOTAL (3*OUT)
#define TSTRIDE 108            // smem row stride (floats): 108%32=12, few conflicts

// Intermediate per-cell result: [3][HO][HO] (+pad for safe over-read)
__device__ float g_mid[3 * HO * HO + 8];

__device__ __forceinline__ unsigned smem_u32(const void* p) {
    unsigned a;
    asm("{ .reg .u64 t; cvta.to.shared.u64 t, %1; cvt.u32.u64 %0, t; }"
        : "=r"(a) : "l"(p));
    return a;
}

// Shared epilogue: packed histogram -> argmax -> fixed-point masked sums.
// Inputs: rv/gv/bv (4 slots, dead slots ignored via bn sentinel), act flags.
__device__ __forceinline__ void cell_reduce_store(
    const float rv[4], const float gv[4], const float bv[4],
    const bool act[4], int wid, int lane)
{
    int bn[4];
    unsigned long long hlo = 0ULL, hhi = 0ULL;
#pragma unroll
    for (int t = 0; t < 4; t++) {
        const float s = __fadd_rn(__fadd_rn(rv[t], gv[t]), bv[t]);
        const int bi = (int)(__fmul_rn(s, 0.020833334f));   // 1/48 rn
        bn[t] = act[t] ? bi : 16;                            // 16 = dead
        if (act[t]) {
            const unsigned long long inc = 1ULL << ((bi & 7) * 8);
            if (bi < 8) hlo += inc; else hhi += inc;
        }
    }

    const unsigned h0 = __reduce_add_sync(0xffffffffu, (unsigned)hlo);
    const unsigned h1 = __reduce_add_sync(0xffffffffu, (unsigned)(hlo >> 32));
    const unsigned h2 = __reduce_add_sync(0xffffffffu, (unsigned)hhi);
    const unsigned h3 = __reduce_add_sync(0xffffffffu, (unsigned)(hhi >> 32));

    // Lane-parallel argmax; ties -> smaller bin (jnp.argmax first-max).
    const int b = lane & 15;
    const unsigned hw = (b < 8) ? ((b < 4) ? h0 : h1) : ((b < 12) ? h2 : h3);
    const unsigned cnt = (hw >> ((b & 3) * 8)) & 0xFFu;
    const unsigned key = (cnt << 4) | (unsigned)(15 - b);
    const unsigned kmax = __reduce_max_sync(0xffffffffu, key);
    const int amax = 15 - (int)(kmax & 15u);
    const float cm = (float)(kmax >> 4);

    // Masked channel sums in 16.16 fixed point (sum < 2^31; err ~1e-7 rel).
    int sri = 0, sgi = 0, sbi = 0;
#pragma unroll
    for (int t = 0; t < 4; t++) {
        if (bn[t] == amax) {
            sri += (int)(rv[t] * 65536.0f);
            sgi += (int)(gv[t] * 65536.0f);
            sbi += (int)(bv[t] * 65536.0f);
        }
    }
    const unsigned sru = __reduce_add_sync(0xffffffffu, (unsigned)sri);
    const unsigned sgu = __reduce_add_sync(0xffffffffu, (unsigned)sgi);
    const unsigned sbu = __reduce_add_sync(0xffffffffu, (unsigned)sbi);

    if (lane == 0) {
        const float inv = __fmul_rn(__frcp_rn(cm), 1.52587890625e-05f);
        g_mid[wid]               = __fmul_rn((float)sru, inv);
        g_mid[wid + HO * HO]     = __fmul_rn((float)sgu, inv);
        g_mid[wid + 2 * HO * HO] = __fmul_rn((float)sbu, inv);
    }
}

// ---------------------------------------------------------------------------
// Kernel 1a: INTERIOR cells (oh>=1, ow0>=8). One block = 8 adjacent cells.
// The 11x96-float window (x3 channels) is fetched by 33 cp.async.bulk copies
// of 384B (16B-aligned: ow0 % 8 == 0 => aligned start = x0b-3) completing on
// an mbarrier — no per-lane load instructions, no L1 wavefront cost.
// Compute reads smem. All window pixels are in-bounds for interior cells.
// ---------------------------------------------------------------------------
__global__ void __launch_bounds__(256) cell_interior_kernel(const float* __restrict__ rgb) {
    __shared__ __align__(16) float tile[3][11][TSTRIDE];
    __shared__ __align__(8) uint64_t mbar;

    const int oh  = 1 + blockIdx.y;                 // 1..204
    const int ow0 = 8 * (1 + blockIdx.x);           // 8..200
    const int tid = threadIdx.x;
    const int w   = tid >> 5;
    const int lane = tid & 31;

    const int y0b = oh * PS - PAD;                  // >= 5
    const int gx0 = ow0 * PS - PAD - 3;             // 16B-aligned float index

    if (tid == 0) {
        asm volatile("mbarrier.init.shared.b64 [%0], 1;"
                     :: "r"(smem_u32(&mbar)) : "memory");
    }
    __syncthreads();

    if (tid == 0) {
        const unsigned mb = smem_u32(&mbar);
        asm volatile("mbarrier.arrive.expect_tx.shared.b64 _, [%0], %1;"
                     :: "r"(mb), "r"(3 * 11 * 384u) : "memory");
#pragma unroll
        for (int ch = 0; ch < 3; ch++) {
            const float* src = rgb + (size_t)ch * (H * W) + (size_t)y0b * W + gx0;
#pragma unroll
            for (int r = 0; r < 11; r++) {
                asm volatile(
                    "cp.async.bulk.shared::cluster.global.mbarrier::complete_tx::bytes "
                    "[%0], [%1], 384, [%2];"
                    :: "r"(smem_u32(&tile[ch][r][0])),
                       "l"(src + (size_t)r * W), "r"(mb) : "memory");
            }
        }
    }

    // Wait (acquire) for all 12672 bytes
    {
        const unsigned mb = smem_u32(&mbar);
        unsigned done;
        asm volatile(
            "{ .reg .pred p; mbarrier.try_wait.parity.acquire.cta.shared::cta.b64 "
            "p, [%1], 0; selp.b32 %0, 1, 0, p; }"
            : "=r"(done) : "r"(mb) : "memory");
        while (!done) {
            asm volatile(
                "{ .reg .pred p; mbarrier.try_wait.parity.acquire.cta.shared::cta.b64 "
                "p, [%1], 0, 0x989680; selp.b32 %0, 1, 0, p; }"
                : "=r"(done) : "r"(mb) : "memory");
        }
    }

    const int ow = ow0 + w;
    if (ow >= HO) return;                           // ow0=200: warps 5-7 idle
    const int wid = oh * HO + ow;
    const int colbase = w * 10 + 3;                 // window x0 within tile

    // p = lane + 32t; 121 px: slots t=0..2 full, t=3 iff lane<25.
    float rv[4], gv[4], bv[4];
    bool act[4];
    act[0] = true; act[1] = true; act[2] = true; act[3] = (lane < 25);
    int dyc[4], cc[4];
#pragma unroll
    for (int t = 0; t < 4; t++) {
        int p = lane + t * 32;
        if (t == 3) p = p > 120 ? 120 : p;          // dup read, masked later
        const int dy = p / KS;
        const int dx = p - dy * KS;
        dyc[t] = dy;
        cc[t] = colbase + dx;
    }
#pragma unroll
    for (int t = 0; t < 4; t++) rv[t] = tile[0][dyc[t]][cc[t]];
#pragma unroll
    for (int t = 0; t < 4; t++) gv[t] = tile[1][dyc[t]][cc[t]];
#pragma unroll
    for (int t = 0; t < 4; t++) bv[t] = tile[2][dyc[t]][cc[t]];

    cell_reduce_store(rv, gv, bv, act, wid, lane);
}

// ---------------------------------------------------------------------------
// Kernel 1b: BORDER cells (oh==0 row-blocks and ow0==0 column-blocks),
// 230 blocks. Proven act-masked direct-LDG path.
// ---------------------------------------------------------------------------
__global__ void __launch_bounds__(256) cell_border_kernel(const float* __restrict__ rgb) {
    const int bx = blockIdx.x;                      // 0..229
    int oh, ow0;
    if (bx < 26) { oh = 0; ow0 = 8 * bx; }
    else         { oh = bx - 25; ow0 = 0; }         // oh = 1..204

    const int w = threadIdx.x >> 5;
    const int lane = threadIdx.x & 31;
    const int ow = ow0 + w;
    if (ow >= HO) return;
    const int wid = oh * HO + ow;

    const int y0 = oh * PS - PAD;
    const int x0 = ow * PS - PAD;

    const float* __restrict__ rp = rgb;
    const float* __restrict__ gp = rgb + H * W;
    const float* __restrict__ bp = rgb + 2 * H * W;

    int off[4];
    bool act[4];
    act[0] = true; act[1] = true; act[2] = true; act[3] = (lane < 25);
#pragma unroll
    for (int t = 0; t < 4; t++) {
        int p = lane + t * 32;
        if (t == 3) p = p > 120 ? 120 : p;
        const int dy = p / KS;
        const int dx = p - dy * KS;
        off[t] = (y0 + dy) * W + (x0 + dx);
        act[t] = act[t] && (y0 + dy >= 0) && (x0 + dx >= 0);
    }

    float rv[4], gv[4], bv[4];
#pragma unroll
    for (int t = 0; t < 4; t++) rv[t] = act[t] ? __ldg(rp + off[t]) : 0.0f;
#pragma unroll
    for (int t = 0; t < 4; t++) gv[t] = act[t] ? __ldg(gp + off[t]) : 0.0f;
#pragma unroll
    for (int t = 0; t < 4; t++) bv[t] = act[t] ? __ldg(bp + off[t]) : 0.0f;

    cell_reduce_store(rv, gv, bv, act, wid, lane);
}

// ---------------------------------------------------------------------------
// Kernel 2: upsample (R4 exact — measured floor 12.6us for this phase).
// ---------------------------------------------------------------------------
__global__ void __launch_bounds__(128) upsample_kernel(float* __restrict__ out) {
    const int row = blockIdx.x;            // 0 .. 3*2255-1
    const int tid = threadIdx.x;
    const unsigned ur = (unsigned)row;
    const unsigned c = ur / (unsigned)OUT;
    const unsigned y = ur - c * (unsigned)OUT;
    const unsigned oh = y / 11u;
    const unsigned ii = y - oh * 11u;

    float* __restrict__ orow = out + (size_t)row * OUT;
    const int h = (int)((4u - ((ur * (unsigned)OUT) & 3u)) & 3u);
    const int nv = (OUT - h) >> 2;
    const int nt = OUT - h - nv * 4;
    float4* __restrict__ ov = (float4*)(orow + h);

    if (ii == 10u) {                       // pad row: zeros
        if (tid < h) orow[tid] = 0.0f;
        if (tid >= 4 && tid < 4 + nt) orow[h + nv * 4 + (tid - 4)] = 0.0f;
        const float4 z = make_float4(0.f, 0.f, 0.f, 0.f);
        for (int v = tid; v < nv; v += 128) ov[v] = z;
        return;
    }

    const float* __restrict__ midc = g_mid + c * HO * HO + oh * HO;

    if (tid < h) orow[tid] = __ldg(midc);
    if (tid >= 4 && tid < 4 + nt) {
        const unsigned x = (unsigned)(h + nv * 4 + (tid - 4));
        const unsigned o = x / 11u;
        const unsigned j = x - o * 11u;
        orow[x] = (j < 10u) ? __ldg(midc + o) : 0.0f;
    }

    for (int v = tid; v < nv; v += 128) {
        const unsigned x0 = (unsigned)(h + v * 4);
        float4 o;
        float* po = &o.x;
#pragma unroll
        for (int k = 0; k < 4; k++) {
            const unsigned x = x0 + (unsigned)k;
            const unsigned o2 = x / 11u;
            const unsigned j = x - o2 * 11u;
            po[k] = (j < 10u) ? __ldg(midc + o2) : 0.0f;
        }
        ov[v] = o;
    }
}

extern "C" void kernel_launch(void* const* d_in, const int* in_sizes, int n_in,
                              void* d_out, int out_size) {
    const float* rgb = (const float*)d_in[0];
    float* out = (float*)d_out;

    dim3 igrid(25, 204);                        // interior: ow0=8..200, oh=1..204
    cell_interior_kernel<<<igrid, 256>>>(rgb);

    cell_border_kernel<<<230, 256>>>(rgb);      // oh==0 and ow0==0 blocks

    upsample_kernel<<<ROWS_TOTAL, 128>>>(out);  // R4 exact
}